// round 8
// baseline (speedup 1.0000x reference)
#include <cuda_runtime.h>

#define N_  2
#define C_  64
#define H_  256
#define W_  256
#define HW  (H_*W_)
#define HD  128
#define WD  128
#define HWD (HD*WD)
#define KK  25
#define KP  28                      // padded k-vector stride (112B, float4-aligned)
#define CGS28 (N_*HWD*KP)           // per-channel-group partial stride (padded)

// scratch (device globals per allocation-free rule)
__device__ __align__(16) float g_w2[KK*64*9];        // folded weights (25,64,3,3)
__device__ __align__(16) float g_tb[KK*9];           // per-tap folded bias
__device__ __align__(16) float g_part[4*CGS28];      // partial logits (padded), 14.7 MB
__device__ __align__(16) float g_k[N_*HWD*KP];       // softmax weights (n,hd,wd,28)
__device__ __align__(16) float g_reasm[N_*256*HWD];  // 33.5 MB (n,c2,hd,wd)

// ---------------------------------------------------------------------------
// Kernel 0: fold down(1x1) into enc(3x3):
//   W2[kk,ci,rs] = sum_c ew[kk,c,rs]*dw[c,ci]
//   TB[kk,rs]    = sum_c ew[kk,c,rs]*db[c]
// ---------------------------------------------------------------------------
__global__ void k_w2(const float* __restrict__ ew,
                     const float* __restrict__ dw,
                     const float* __restrict__ db) {
    __shared__ float sew[576];
    __shared__ float sdb[64];
    __shared__ float sdw[64*64];
    const int kk = blockIdx.x;
    const int t  = threadIdx.x;
    sew[t] = ew[kk*576 + t];
    if (t < 64) sdb[t] = db[t];
    for (int i = t; i < 4096; i += 576) sdw[i] = dw[i];
    __syncthreads();

    const int ci = t / 9, rs = t % 9;
    float s = 0.f;
#pragma unroll 8
    for (int c = 0; c < 64; c++) s += sew[c*9 + rs] * sdw[c*64 + ci];
    g_w2[kk*576 + ci*9 + rs] = s;

    if (t < 9) {
        float s2 = 0.f;
        for (int c = 0; c < 64; c++) s2 += sew[c*9 + t] * sdb[c];
        g_tb[kk*9 + t] = s2;
    }
}

// ---------------------------------------------------------------------------
// Kernel 1: folded 3x3 stride-2 conv x(64ch) -> 25 partial logits.
// Channel-split x4: grid (8,8,8), z = n*4+cg, 16 ch/block. Writes padded.
// ---------------------------------------------------------------------------
__global__ void __launch_bounds__(128) k_enc(const float* __restrict__ x) {
    __shared__ float tile[33][36];
    __shared__ float ws[25][9];
    const int n   = blockIdx.z >> 2;
    const int cg  = blockIdx.z & 3;
    const int hd0 = blockIdx.y * 16;
    const int wd0 = blockIdx.x * 16;
    const int tid = threadIdx.x;           // 128
    const int tx  = tid & 15;
    const int ty  = tid >> 4;              // 0..7 -> hd pair

    float acc0[KK], acc1[KK];
#pragma unroll
    for (int kk = 0; kk < KK; kk++) { acc0[kk] = 0.f; acc1[kk] = 0.f; }

    const int h0 = 2 * hd0 - 1;
    const int w0 = 2 * wd0 - 1;
    const float* src = x + n * C_ * HW;
    const int c0 = cg * 16;

    for (int c = c0; c < c0 + 16; c++) {
        for (int idx = tid; idx < 33 * 33; idx += 128) {
            int r = idx / 33, cc = idx % 33;
            int h = h0 + r, w = w0 + cc;
            tile[r][cc] = (h >= 0 && h < H_ && w >= 0 && w < W_)
                          ? src[c * HW + h * W_ + w] : 0.f;
        }
        for (int idx = tid; idx < 225; idx += 128)
            ws[idx / 9][idx % 9] = g_w2[(idx / 9) * 576 + c * 9 + (idx % 9)];
        __syncthreads();

        float v0[9], v1[9];
#pragma unroll
        for (int r = 0; r < 3; r++)
#pragma unroll
            for (int s = 0; s < 3; s++) {
                v0[r * 3 + s] = tile[4 * ty + r][2 * tx + s];
                v1[r * 3 + s] = tile[4 * ty + 2 + r][2 * tx + s];
            }
#pragma unroll
        for (int kk = 0; kk < KK; kk++) {
            float s0 = 0.f, s1 = 0.f;
#pragma unroll
            for (int t = 0; t < 9; t++) {
                float wv = ws[kk][t];
                s0 += wv * v0[t];
                s1 += wv * v1[t];
            }
            acc0[kk] += s0; acc1[kk] += s1;
        }
        __syncthreads();
    }

    const int wd = wd0 + tx;
    {
        int hd = hd0 + 2 * ty;
        float* dst = g_part + cg * CGS28 + ((n * HD + hd) * WD + wd) * KP;
#pragma unroll
        for (int kk = 0; kk < KK; kk++) dst[kk] = acc0[kk];
    }
    {
        int hd = hd0 + 2 * ty + 1;
        float* dst = g_part + cg * CGS28 + ((n * HD + hd) * WD + wd) * KP;
#pragma unroll
        for (int kk = 0; kk < KK; kk++) dst[kk] = acc1[kk];
    }
}

// ---------------------------------------------------------------------------
// Kernel 2: sum 4 partials + bias (padding-aware tap bias) + softmax.
// float4 loads/stores on the padded 28-float layout.
// ---------------------------------------------------------------------------
__global__ void __launch_bounds__(256) k_softmax(const float* __restrict__ eb) {
    __shared__ float stb[225];
    __shared__ float seb[25];
    const int tid = threadIdx.x;
    if (tid < 225) stb[tid] = g_tb[tid];
    if (tid < 25)  seb[tid] = eb[tid];
    __syncthreads();

    const int pix = blockIdx.x * 256 + tid;           // 32768 pixels
    const int wd = pix & 127;
    const int hd = (pix >> 7) & 127;

    // tap validity: only top/left edge clips (stride2, pad1, k=3)
    const float r0 = (hd != 0) ? 1.f : 0.f;
    const float s0 = (wd != 0) ? 1.f : 0.f;
    float m9[9];
    m9[0] = r0 * s0; m9[1] = r0; m9[2] = r0;
    m9[3] = s0;      m9[4] = 1.f; m9[5] = 1.f;
    m9[6] = s0;      m9[7] = 1.f; m9[8] = 1.f;

    const float4* p0 = (const float4*)(g_part + (size_t)pix * KP);
    const float4* p1 = (const float4*)(g_part + CGS28   + (size_t)pix * KP);
    const float4* p2 = (const float4*)(g_part + 2*CGS28 + (size_t)pix * KP);
    const float4* p3 = (const float4*)(g_part + 3*CGS28 + (size_t)pix * KP);
    float a[28];
#pragma unroll
    for (int i = 0; i < 7; i++) {
        float4 v0 = p0[i], v1 = p1[i], v2 = p2[i], v3 = p3[i];
        a[4*i+0] = v0.x + v1.x + v2.x + v3.x;
        a[4*i+1] = v0.y + v1.y + v2.y + v3.y;
        a[4*i+2] = v0.z + v1.z + v2.z + v3.z;
        a[4*i+3] = v0.w + v1.w + v2.w + v3.w;
    }

    float lg[28];
#pragma unroll
    for (int kk = 0; kk < KK; kk++) {
        float v = a[kk] + seb[kk];
#pragma unroll
        for (int t = 0; t < 9; t++) v += m9[t] * stb[kk*9 + t];
        lg[kk] = v;
    }

    float mx = lg[0];
#pragma unroll
    for (int kk = 1; kk < KK; kk++) mx = fmaxf(mx, lg[kk]);
    float sum = 0.f;
#pragma unroll
    for (int kk = 0; kk < KK; kk++) { lg[kk] = expf(lg[kk] - mx); sum += lg[kk]; }
    float inv = 1.f / sum;
#pragma unroll
    for (int kk = 0; kk < KK; kk++) lg[kk] *= inv;
    lg[25] = 0.f; lg[26] = 0.f; lg[27] = 0.f;

    float4* dst = (float4*)(g_k + (size_t)pix * KP);
#pragma unroll
    for (int i = 0; i < 7; i++)
        dst[i] = make_float4(lg[4*i], lg[4*i+1], lg[4*i+2], lg[4*i+3]);
}

// ---------------------------------------------------------------------------
// Kernel 3: weighted 5x5 reassembly with row-major-reshape remap.
// src pixel = x[c2>>2, (c2&3)*64 + (hd>>1)+di-2, 128*(hd&1)+wd+dj-2]
// Block = (hd-tile of 4, c-group of 8, n). kw weights loaded ONCE into
// registers (float4 on padded layout) and reused across 8 channels ->
// 8x less g_k traffic and 8x fewer kw-load instructions. Staging is
// div-free: 24 unrolled coalesced row copies.
// ---------------------------------------------------------------------------
__global__ void __launch_bounds__(256, 2) k_reasm(const float* __restrict__ x) {
    __shared__ float xt[4][6][260];
    const int n   = blockIdx.z;
    const int cg  = blockIdx.y;          // 0..7 -> channels cg*8..cg*8+7
    const int hd0 = blockIdx.x * 4;
    const int tid = threadIdx.x;         // 256

    const int wd  = tid & 127;
    const int ph  = tid >> 7;            // 0..1
    const int hdA = hd0 + ph;            // xt rows 0..4
    const int hdB = hd0 + ph + 2;        // xt rows 1..5 (same parity)
    const int col0 = ((hdA & 1) << 7) + wd;
    const int rbase = (hd0 >> 1) - 2;

    // load both pixels' 25 softmax weights once (7 LDG.128 each)
    float kwA[25], kwB[25];
    {
        const float4* kpA = (const float4*)(g_k + (size_t)((n * HD + hdA) * WD + wd) * KP);
        const float4* kpB = (const float4*)(g_k + (size_t)((n * HD + hdB) * WD + wd) * KP);
        float tA[28], tB[28];
#pragma unroll
        for (int i = 0; i < 7; i++) {
            float4 va = kpA[i], vb = kpB[i];
            tA[4*i] = va.x; tA[4*i+1] = va.y; tA[4*i+2] = va.z; tA[4*i+3] = va.w;
            tB[4*i] = vb.x; tB[4*i+1] = vb.y; tB[4*i+2] = vb.z; tB[4*i+3] = vb.w;
        }
#pragma unroll
        for (int kk = 0; kk < KK; kk++) { kwA[kk] = tA[kk]; kwB[kk] = tB[kk]; }
    }

    for (int ci = 0; ci < 8; ci++) {
        const int c = cg * 8 + ci;
        const float* src = x + (size_t)(n * C_ + c) * HW;

        __syncthreads();   // previous iteration's xt reads done
        // div-free staging: 24 rows (4 quadrants x 6), 260 cols each
#pragma unroll
        for (int qr = 0; qr < 24; qr++) {
            const int q  = qr / 6;       // compile-time (unrolled)
            const int rl = qr % 6;
            const int h = q * 64 + rbase + rl;
            const bool hv = (h >= 0) && (h < H_);
            const float* rowp = src + h * W_;
            const int w = tid - 2;
            xt[q][rl][tid] = (hv && w >= 0) ? rowp[w] : 0.f;
            if (tid < 4) {
                const int w2 = 254 + tid;
                xt[q][rl][256 + tid] = (hv && w2 < W_) ? rowp[w2] : 0.f;
            }
        }
        __syncthreads();

#pragma unroll
        for (int q = 0; q < 4; q++) {
            float sA = 0.f, sB = 0.f;
#pragma unroll
            for (int dj = 0; dj < 5; dj++) {
                float v[6];
#pragma unroll
                for (int r = 0; r < 6; r++) v[r] = xt[q][r][col0 + dj];
#pragma unroll
                for (int di = 0; di < 5; di++) {
                    sA += kwA[di * 5 + dj] * v[di];
                    sB += kwB[di * 5 + dj] * v[di + 1];
                }
            }
            g_reasm[(size_t)((n * 256 + c * 4 + q) * HD + hdA) * WD + wd] = sA;
            g_reasm[(size_t)((n * 256 + c * 4 + q) * HD + hdB) * WD + wd] = sB;
        }
    }
}

// ---------------------------------------------------------------------------
// Kernel 4: 1x1 conv 256->64. Tile 64 cout x 128 px, 256 threads,
// 4 cout x 8 px per thread, float4 smem loads.
// ---------------------------------------------------------------------------
__global__ void __launch_bounds__(256) k_out(const float* __restrict__ w,
                                             const float* __restrict__ b,
                                             float* __restrict__ out) {
    __shared__ float Xs[32][128];    // [k][pixel]
    __shared__ float Wr[64][33];     // [cout][k] (padded)
    const int tid  = threadIdx.x;
    const int n    = blockIdx.x >> 7;          // 128 pixel-blocks per n
    const int p0   = (blockIdx.x & 127) << 7;  // 128 pixels
    const int px16 = tid & 15;                 // pixel quad base
    const int chg  = tid >> 4;                 // cout quad (0..15)

    float acc[2][4][4];                        // [half][pi][co]
#pragma unroll
    for (int co = 0; co < 4; co++) {
        float bv = b[chg * 4 + co];
#pragma unroll
        for (int h = 0; h < 2; h++)
#pragma unroll
            for (int pi = 0; pi < 4; pi++) acc[h][pi][co] = bv;
    }

    for (int kb = 0; kb < 8; kb++) {
        __syncthreads();
#pragma unroll
        for (int i = 0; i < 4; i++) {
            int f   = tid + i * 256;
            int row = f >> 5;
            int col = (f & 31) * 4;
            float4 v = *(const float4*)&g_reasm[(size_t)(n*256 + kb*32 + row) * HWD + p0 + col];
            *(float4*)&Xs[row][col] = v;
        }
#pragma unroll
        for (int i = 0; i < 2; i++) {
            int f    = tid + i * 256;
            int cout = f >> 3;
            int kg   = f & 7;
            float4 v = *(const float4*)&w[cout * 256 + kb * 32 + kg * 4];
            Wr[cout][kg*4+0] = v.x; Wr[cout][kg*4+1] = v.y;
            Wr[cout][kg*4+2] = v.z; Wr[cout][kg*4+3] = v.w;
        }
        __syncthreads();

#pragma unroll 8
        for (int kc = 0; kc < 32; kc++) {
            float4 xa = *(const float4*)&Xs[kc][px16 * 4];
            float4 xb = *(const float4*)&Xs[kc][64 + px16 * 4];
            float w0 = Wr[chg*4+0][kc], w1 = Wr[chg*4+1][kc];
            float w2 = Wr[chg*4+2][kc], w3 = Wr[chg*4+3][kc];
            float xv[2][4] = {{xa.x, xa.y, xa.z, xa.w}, {xb.x, xb.y, xb.z, xb.w}};
#pragma unroll
            for (int h = 0; h < 2; h++)
#pragma unroll
                for (int pi = 0; pi < 4; pi++) {
                    acc[h][pi][0] += xv[h][pi] * w0;
                    acc[h][pi][1] += xv[h][pi] * w1;
                    acc[h][pi][2] += xv[h][pi] * w2;
                    acc[h][pi][3] += xv[h][pi] * w3;
                }
        }
    }

#pragma unroll
    for (int co = 0; co < 4; co++) {
        int cg = chg * 4 + co;
#pragma unroll
        for (int h = 0; h < 2; h++) {
            float4 v = make_float4(acc[h][0][co], acc[h][1][co],
                                   acc[h][2][co], acc[h][3][co]);
            *(float4*)&out[(size_t)(n*64 + cg) * HWD + p0 + h*64 + px16*4] = v;
        }
    }
}

// ---------------------------------------------------------------------------
extern "C" void kernel_launch(void* const* d_in, const int* in_sizes, int n_in,
                              void* d_out, int out_size) {
    const float* x      = (const float*)d_in[0];
    const float* down_w = (const float*)d_in[1];
    const float* down_b = (const float*)d_in[2];
    const float* enc_w  = (const float*)d_in[3];
    const float* enc_b  = (const float*)d_in[4];
    const float* out_w  = (const float*)d_in[5];
    const float* out_b  = (const float*)d_in[6];
    float* out = (float*)d_out;

    k_w2<<<25, 576>>>(enc_w, down_w, down_b);

    dim3 g1(8, 8, 8);                 // z = n*4 + channel-group
    k_enc<<<g1, 128>>>(x);

    k_softmax<<<128, 256>>>(enc_b);

    dim3 g3(32, 8, 2);                // hd-tiles x c-groups x n
    k_reasm<<<g3, 256>>>(x);

    k_out<<<256, 256>>>(out_w, out_b, out);
}

// round 9
// speedup vs baseline: 1.5605x; 1.5605x over previous
#include <cuda_runtime.h>
#include <cstdint>

#define N_  2
#define C_  64
#define H_  256
#define W_  256
#define HW  (H_*W_)
#define HD  128
#define WD  128
#define HWD (HD*WD)
#define KK  25
#define KP  28                      // padded k-vector stride (112B, float4-aligned)
#define CGS28 (N_*HWD*KP)           // per-channel-group partial stride (padded)

// scratch (device globals per allocation-free rule)
__device__ __align__(16) float g_w2[KK*64*9];        // folded weights (25,64,3,3)
__device__ __align__(16) float g_tb[KK*9];           // per-tap folded bias
__device__ __align__(16) float g_part[4*CGS28];      // partial logits (padded), 14.7 MB
__device__ __align__(16) float g_k[N_*HWD*KP];       // softmax weights (n,hd,wd,28)
__device__ __align__(16) float g_reasm[N_*256*HWD];  // 33.5 MB (n,c2,hd,wd)

// cp.async 4B with zero-fill when invalid (src_size=0 -> no memory access, zeros)
__device__ __forceinline__ void cp_async4(uint32_t dst_smem, const void* src, bool valid) {
    int sz = valid ? 4 : 0;
    asm volatile("cp.async.ca.shared.global [%0], [%1], 4, %2;\n"
                 :: "r"(dst_smem), "l"(src), "r"(sz));
}
__device__ __forceinline__ void cp_async_commit() {
    asm volatile("cp.async.commit_group;\n");
}

// ---------------------------------------------------------------------------
// Kernel 0: fold down(1x1) into enc(3x3):
//   W2[kk,ci,rs] = sum_c ew[kk,c,rs]*dw[c,ci]
//   TB[kk,rs]    = sum_c ew[kk,c,rs]*db[c]
// ---------------------------------------------------------------------------
__global__ void k_w2(const float* __restrict__ ew,
                     const float* __restrict__ dw,
                     const float* __restrict__ db) {
    __shared__ float sew[576];
    __shared__ float sdb[64];
    __shared__ float sdw[64*64];
    const int kk = blockIdx.x;
    const int t  = threadIdx.x;
    sew[t] = ew[kk*576 + t];
    if (t < 64) sdb[t] = db[t];
    for (int i = t; i < 4096; i += 576) sdw[i] = dw[i];
    __syncthreads();

    const int ci = t / 9, rs = t % 9;
    float s = 0.f;
#pragma unroll 8
    for (int c = 0; c < 64; c++) s += sew[c*9 + rs] * sdw[c*64 + ci];
    g_w2[kk*576 + ci*9 + rs] = s;

    if (t < 9) {
        float s2 = 0.f;
        for (int c = 0; c < 64; c++) s2 += sew[c*9 + t] * sdb[c];
        g_tb[kk*9 + t] = s2;
    }
}

// ---------------------------------------------------------------------------
// Kernel 1: folded 3x3 stride-2 conv x(64ch) -> 25 partial logits.
// Channel-split x4: grid (8,8,8), z = n*4+cg, 16 ch/block. Writes padded.
// ---------------------------------------------------------------------------
__global__ void __launch_bounds__(128) k_enc(const float* __restrict__ x) {
    __shared__ float tile[33][36];
    __shared__ float ws[25][9];
    const int n   = blockIdx.z >> 2;
    const int cg  = blockIdx.z & 3;
    const int hd0 = blockIdx.y * 16;
    const int wd0 = blockIdx.x * 16;
    const int tid = threadIdx.x;           // 128
    const int tx  = tid & 15;
    const int ty  = tid >> 4;              // 0..7 -> hd pair

    float acc0[KK], acc1[KK];
#pragma unroll
    for (int kk = 0; kk < KK; kk++) { acc0[kk] = 0.f; acc1[kk] = 0.f; }

    const int h0 = 2 * hd0 - 1;
    const int w0 = 2 * wd0 - 1;
    const float* src = x + n * C_ * HW;
    const int c0 = cg * 16;

    for (int c = c0; c < c0 + 16; c++) {
        for (int idx = tid; idx < 33 * 33; idx += 128) {
            int r = idx / 33, cc = idx % 33;
            int h = h0 + r, w = w0 + cc;
            tile[r][cc] = (h >= 0 && h < H_ && w >= 0 && w < W_)
                          ? src[c * HW + h * W_ + w] : 0.f;
        }
        for (int idx = tid; idx < 225; idx += 128)
            ws[idx / 9][idx % 9] = g_w2[(idx / 9) * 576 + c * 9 + (idx % 9)];
        __syncthreads();

        float v0[9], v1[9];
#pragma unroll
        for (int r = 0; r < 3; r++)
#pragma unroll
            for (int s = 0; s < 3; s++) {
                v0[r * 3 + s] = tile[4 * ty + r][2 * tx + s];
                v1[r * 3 + s] = tile[4 * ty + 2 + r][2 * tx + s];
            }
#pragma unroll
        for (int kk = 0; kk < KK; kk++) {
            float s0 = 0.f, s1 = 0.f;
#pragma unroll
            for (int t = 0; t < 9; t++) {
                float wv = ws[kk][t];
                s0 += wv * v0[t];
                s1 += wv * v1[t];
            }
            acc0[kk] += s0; acc1[kk] += s1;
        }
        __syncthreads();
    }

    const int wd = wd0 + tx;
    {
        int hd = hd0 + 2 * ty;
        float* dst = g_part + cg * CGS28 + ((n * HD + hd) * WD + wd) * KP;
#pragma unroll
        for (int kk = 0; kk < KK; kk++) dst[kk] = acc0[kk];
    }
    {
        int hd = hd0 + 2 * ty + 1;
        float* dst = g_part + cg * CGS28 + ((n * HD + hd) * WD + wd) * KP;
#pragma unroll
        for (int kk = 0; kk < KK; kk++) dst[kk] = acc1[kk];
    }
}

// ---------------------------------------------------------------------------
// Kernel 2: sum 4 partials + bias (padding-aware tap bias) + softmax.
// float4 loads/stores on the padded 28-float layout.
// ---------------------------------------------------------------------------
__global__ void __launch_bounds__(256) k_softmax(const float* __restrict__ eb) {
    __shared__ float stb[225];
    __shared__ float seb[25];
    const int tid = threadIdx.x;
    if (tid < 225) stb[tid] = g_tb[tid];
    if (tid < 25)  seb[tid] = eb[tid];
    __syncthreads();

    const int pix = blockIdx.x * 256 + tid;           // 32768 pixels
    const int wd = pix & 127;
    const int hd = (pix >> 7) & 127;

    // tap validity: only top/left edge clips (stride2, pad1, k=3)
    const float r0 = (hd != 0) ? 1.f : 0.f;
    const float s0 = (wd != 0) ? 1.f : 0.f;
    float m9[9];
    m9[0] = r0 * s0; m9[1] = r0; m9[2] = r0;
    m9[3] = s0;      m9[4] = 1.f; m9[5] = 1.f;
    m9[6] = s0;      m9[7] = 1.f; m9[8] = 1.f;

    const float4* p0 = (const float4*)(g_part + (size_t)pix * KP);
    const float4* p1 = (const float4*)(g_part + CGS28   + (size_t)pix * KP);
    const float4* p2 = (const float4*)(g_part + 2*CGS28 + (size_t)pix * KP);
    const float4* p3 = (const float4*)(g_part + 3*CGS28 + (size_t)pix * KP);
    float a[28];
#pragma unroll
    for (int i = 0; i < 7; i++) {
        float4 v0 = p0[i], v1 = p1[i], v2 = p2[i], v3 = p3[i];
        a[4*i+0] = v0.x + v1.x + v2.x + v3.x;
        a[4*i+1] = v0.y + v1.y + v2.y + v3.y;
        a[4*i+2] = v0.z + v1.z + v2.z + v3.z;
        a[4*i+3] = v0.w + v1.w + v2.w + v3.w;
    }

    float lg[28];
#pragma unroll
    for (int kk = 0; kk < KK; kk++) {
        float v = a[kk] + seb[kk];
#pragma unroll
        for (int t = 0; t < 9; t++) v += m9[t] * stb[kk*9 + t];
        lg[kk] = v;
    }

    float mx = lg[0];
#pragma unroll
    for (int kk = 1; kk < KK; kk++) mx = fmaxf(mx, lg[kk]);
    float sum = 0.f;
#pragma unroll
    for (int kk = 0; kk < KK; kk++) { lg[kk] = expf(lg[kk] - mx); sum += lg[kk]; }
    float inv = 1.f / sum;
#pragma unroll
    for (int kk = 0; kk < KK; kk++) lg[kk] *= inv;
    lg[25] = 0.f; lg[26] = 0.f; lg[27] = 0.f;

    float4* dst = (float4*)(g_k + (size_t)pix * KP);
#pragma unroll
    for (int i = 0; i < 7; i++)
        dst[i] = make_float4(lg[4*i], lg[4*i+1], lg[4*i+2], lg[4*i+3]);
}

// ---------------------------------------------------------------------------
// Kernel 3: weighted 5x5 reassembly, cp.async double-buffered pipeline.
// src pixel = x[c2>>2, (c2&3)*64 + (hd>>1)+di-2, 128*(hd&1)+wd+dj-2]
// Block = (hd-tile of 4, c-group of 4, n) -> grid 1024. Stage channel c+2
// into the idle buffer while computing channel c; edge zero-fill via
// cp.async src_size=0. kw in regs, reused over 4 channels.
// Dynamic smem: 2 buffers x 4q x 6rows x 260cols = 49,920 B.
// ---------------------------------------------------------------------------
#define XT_ROWSZ 260
#define XT_BUF   (4*6*XT_ROWSZ)          // floats per buffer = 6240

__global__ void __launch_bounds__(256, 2) k_reasm(const float* __restrict__ x) {
    extern __shared__ float xs[];        // xs[2][4][6][260]
    const int n   = blockIdx.z;
    const int cg  = blockIdx.y;          // 0..15 -> channels cg*4..cg*4+3
    const int hd0 = blockIdx.x * 4;
    const int tid = threadIdx.x;         // 256

    const int wd  = tid & 127;
    const int ph  = tid >> 7;            // 0..1
    const int hdA = hd0 + ph;            // xt rows 0..4
    const int hdB = hd0 + ph + 2;        // xt rows 1..5 (same parity)
    const int col0 = ((hdA & 1) << 7) + wd;
    const int rbase = (hd0 >> 1) - 2;

    const uint32_t smem_u32 = (uint32_t)__cvta_generic_to_shared(xs);

    // load both pixels' 25 softmax weights once (7 LDG.128 each)
    float kwA[25], kwB[25];
    {
        const float4* kpA = (const float4*)(g_k + (size_t)((n * HD + hdA) * WD + wd) * KP);
        const float4* kpB = (const float4*)(g_k + (size_t)((n * HD + hdB) * WD + wd) * KP);
        float tA[28], tB[28];
#pragma unroll
        for (int i = 0; i < 7; i++) {
            float4 va = kpA[i], vb = kpB[i];
            tA[4*i] = va.x; tA[4*i+1] = va.y; tA[4*i+2] = va.z; tA[4*i+3] = va.w;
            tB[4*i] = vb.x; tB[4*i+1] = vb.y; tB[4*i+2] = vb.z; tB[4*i+3] = vb.w;
        }
#pragma unroll
        for (int kk = 0; kk < KK; kk++) { kwA[kk] = tA[kk]; kwB[kk] = tB[kk]; }
    }

    const float* xn = x + (size_t)n * C_ * HW;

    // stage channel (cg*4+ci) into buffer buf
    auto stage = [&](int ci, int buf) {
        const float* src = xn + (size_t)(cg * 4 + ci) * HW;
        const uint32_t base = smem_u32 + (uint32_t)buf * (XT_BUF * 4);
#pragma unroll
        for (int qr = 0; qr < 24; qr++) {
            const int q  = qr / 6;                 // compile-time (unrolled)
            const int rl = qr % 6;
            const int h = q * 64 + rbase + rl;
            const bool hv = (h >= 0) && (h < H_);
            const float* rowp = src + h * W_;
            const int w = tid - 2;
            cp_async4(base + (uint32_t)(qr * XT_ROWSZ + tid) * 4,
                      rowp + w, hv && (w >= 0));
            if (tid < 4) {
                const int w2 = 254 + tid;
                cp_async4(base + (uint32_t)(qr * XT_ROWSZ + 256 + tid) * 4,
                          rowp + w2, hv && (w2 < W_));
            }
        }
        cp_async_commit();
    };

    stage(0, 0);
    stage(1, 1);

#pragma unroll
    for (int ci = 0; ci < 4; ci++) {
        if (ci == 3) asm volatile("cp.async.wait_group 0;\n");
        else         asm volatile("cp.async.wait_group 1;\n");
        __syncthreads();                          // buffer ci&1 ready for all

        const float* xb = xs + (ci & 1) * XT_BUF;
        const int c = cg * 4 + ci;

#pragma unroll
        for (int q = 0; q < 4; q++) {
            float sA = 0.f, sB = 0.f;
            const float* qb = xb + q * (6 * XT_ROWSZ) + col0;
#pragma unroll
            for (int dj = 0; dj < 5; dj++) {
                float v[6];
#pragma unroll
                for (int r = 0; r < 6; r++) v[r] = qb[r * XT_ROWSZ + dj];
#pragma unroll
                for (int di = 0; di < 5; di++) {
                    sA += kwA[di * 5 + dj] * v[di];
                    sB += kwB[di * 5 + dj] * v[di + 1];
                }
            }
            g_reasm[(size_t)((n * 256 + c * 4 + q) * HD + hdA) * WD + wd] = sA;
            g_reasm[(size_t)((n * 256 + c * 4 + q) * HD + hdB) * WD + wd] = sB;
        }

        if (ci < 2) {
            __syncthreads();                      // all done reading buffer ci&1
            stage(ci + 2, ci & 1);                // overwrite it with c+2
        }
    }
}

// ---------------------------------------------------------------------------
// Kernel 4: 1x1 conv 256->64. Tile 64 cout x 128 px, 256 threads,
// 4 cout x 8 px per thread, float4 smem loads.
// ---------------------------------------------------------------------------
__global__ void __launch_bounds__(256) k_out(const float* __restrict__ w,
                                             const float* __restrict__ b,
                                             float* __restrict__ out) {
    __shared__ float Xs[32][128];    // [k][pixel]
    __shared__ float Wr[64][33];     // [cout][k] (padded)
    const int tid  = threadIdx.x;
    const int n    = blockIdx.x >> 7;          // 128 pixel-blocks per n
    const int p0   = (blockIdx.x & 127) << 7;  // 128 pixels
    const int px16 = tid & 15;                 // pixel quad base
    const int chg  = tid >> 4;                 // cout quad (0..15)

    float acc[2][4][4];                        // [half][pi][co]
#pragma unroll
    for (int co = 0; co < 4; co++) {
        float bv = b[chg * 4 + co];
#pragma unroll
        for (int h = 0; h < 2; h++)
#pragma unroll
            for (int pi = 0; pi < 4; pi++) acc[h][pi][co] = bv;
    }

    for (int kb = 0; kb < 8; kb++) {
        __syncthreads();
#pragma unroll
        for (int i = 0; i < 4; i++) {
            int f   = tid + i * 256;
            int row = f >> 5;
            int col = (f & 31) * 4;
            float4 v = *(const float4*)&g_reasm[(size_t)(n*256 + kb*32 + row) * HWD + p0 + col];
            *(float4*)&Xs[row][col] = v;
        }
#pragma unroll
        for (int i = 0; i < 2; i++) {
            int f    = tid + i * 256;
            int cout = f >> 3;
            int kg   = f & 7;
            float4 v = *(const float4*)&w[cout * 256 + kb * 32 + kg * 4];
            Wr[cout][kg*4+0] = v.x; Wr[cout][kg*4+1] = v.y;
            Wr[cout][kg*4+2] = v.z; Wr[cout][kg*4+3] = v.w;
        }
        __syncthreads();

#pragma unroll 8
        for (int kc = 0; kc < 32; kc++) {
            float4 xa = *(const float4*)&Xs[kc][px16 * 4];
            float4 xb = *(const float4*)&Xs[kc][64 + px16 * 4];
            float w0 = Wr[chg*4+0][kc], w1 = Wr[chg*4+1][kc];
            float w2 = Wr[chg*4+2][kc], w3 = Wr[chg*4+3][kc];
            float xv[2][4] = {{xa.x, xa.y, xa.z, xa.w}, {xb.x, xb.y, xb.z, xb.w}};
#pragma unroll
            for (int h = 0; h < 2; h++)
#pragma unroll
                for (int pi = 0; pi < 4; pi++) {
                    acc[h][pi][0] += xv[h][pi] * w0;
                    acc[h][pi][1] += xv[h][pi] * w1;
                    acc[h][pi][2] += xv[h][pi] * w2;
                    acc[h][pi][3] += xv[h][pi] * w3;
                }
        }
    }

#pragma unroll
    for (int co = 0; co < 4; co++) {
        int cg = chg * 4 + co;
#pragma unroll
        for (int h = 0; h < 2; h++) {
            float4 v = make_float4(acc[h][0][co], acc[h][1][co],
                                   acc[h][2][co], acc[h][3][co]);
            *(float4*)&out[(size_t)(n*64 + cg) * HWD + p0 + h*64 + px16*4] = v;
        }
    }
}

// ---------------------------------------------------------------------------
extern "C" void kernel_launch(void* const* d_in, const int* in_sizes, int n_in,
                              void* d_out, int out_size) {
    const float* x      = (const float*)d_in[0];
    const float* down_w = (const float*)d_in[1];
    const float* down_b = (const float*)d_in[2];
    const float* enc_w  = (const float*)d_in[3];
    const float* enc_b  = (const float*)d_in[4];
    const float* out_w  = (const float*)d_in[5];
    const float* out_b  = (const float*)d_in[6];
    float* out = (float*)d_out;

    static bool attr_set = false;
    if (!attr_set) {
        cudaFuncSetAttribute(k_reasm, cudaFuncAttributeMaxDynamicSharedMemorySize,
                             2 * XT_BUF * 4);
        attr_set = true;
    }

    k_w2<<<25, 576>>>(enc_w, down_w, down_b);

    dim3 g1(8, 8, 8);                 // z = n*4 + channel-group
    k_enc<<<g1, 128>>>(x);

    k_softmax<<<128, 256>>>(enc_b);

    dim3 g3(32, 16, 2);               // hd-tiles x c-groups(4ch) x n
    k_reasm<<<g3, 256, 2 * XT_BUF * 4>>>(x);

    k_out<<<256, 256>>>(out_w, out_b, out);
}